// round 4
// baseline (speedup 1.0000x reference)
#include <cuda_runtime.h>
#include <cuda_bf16.h>
#include <cstdint>

// Sparse average pooling, output-driven two-phase:
//   Phase A: zero per-output counters (int4)
//   Phase B: invert rulebook into fixed-capacity buckets (vectorized, atomic slot alloc)
//   Phase C: per-output gather, 8 threads/output x 2 float4 chunks (MLP=8)
// Output written exactly once: no memset, no output atomics.

#define CAP 32
#define NOUT_CAP 400000
#define NRULE_CAP 1600000

__device__ int g_counts[NOUT_CAP];
__device__ int g_bucket[(size_t)NOUT_CAP * CAP];

__global__ void zero_counts_kernel(int n_words4)
{
    int i = blockIdx.x * blockDim.x + threadIdx.x;
    if (i < n_words4)
        reinterpret_cast<int4*>(g_counts)[i] = make_int4(0, 0, 0, 0);
}

__global__ void bucket_scatter_kernel(const int* __restrict__ rules_in,
                                      const int* __restrict__ rules_out,
                                      int n_rules)
{
    int t = blockIdx.x * blockDim.x + threadIdx.x;
    int base = t * 4;
    if (base >= n_rules) return;

    if (base + 4 <= n_rules) {
        int4 ri = *reinterpret_cast<const int4*>(rules_in  + base);
        int4 ro = *reinterpret_cast<const int4*>(rules_out + base);
        int s;
        s = atomicAdd(&g_counts[ro.x], 1); if (s < CAP) g_bucket[(size_t)ro.x * CAP + s] = ri.x;
        s = atomicAdd(&g_counts[ro.y], 1); if (s < CAP) g_bucket[(size_t)ro.y * CAP + s] = ri.y;
        s = atomicAdd(&g_counts[ro.z], 1); if (s < CAP) g_bucket[(size_t)ro.z * CAP + s] = ri.z;
        s = atomicAdd(&g_counts[ro.w], 1); if (s < CAP) g_bucket[(size_t)ro.w * CAP + s] = ri.w;
    } else {
        for (int r = base; r < n_rules; r++) {
            int ro = rules_out[r];
            int s = atomicAdd(&g_counts[ro], 1);
            if (s < CAP) g_bucket[(size_t)ro * CAP + s] = rules_in[r];
        }
    }
}

__global__ void gather_kernel(const float* __restrict__ input,
                              float* __restrict__ out,
                              int n_out)
{
    const float scale = 0.125f;   // 1 / POOL_VOLUME

    long long gid = (long long)blockIdx.x * blockDim.x + threadIdx.x;
    int o = (int)(gid >> 3);      // output row
    int c = (int)(gid & 7);       // this thread owns float4 chunks c and c+8
    if (o >= n_out) return;

    int n = g_counts[o];
    if (n > CAP) n = CAP;

    const int4*   bk4 = reinterpret_cast<const int4*>(g_bucket + (size_t)o * CAP);
    const float4* in4 = reinterpret_cast<const float4*>(input);

    float4 accA = make_float4(0.f, 0.f, 0.f, 0.f);
    float4 accB = make_float4(0.f, 0.f, 0.f, 0.f);

    for (int base = 0; base < n; base += 4) {
        int4 idx = __ldcs(bk4 + (base >> 2));
        int m = n - base;
        bool p1 = (m > 1), p2 = (m > 2), p3 = (m > 3);

        const float4* r0 = in4 + (size_t)idx.x * 16;
        const float4* r1 = in4 + (size_t)idx.y * 16;
        const float4* r2 = in4 + (size_t)idx.z * 16;
        const float4* r3 = in4 + (size_t)idx.w * 16;

        // 8 independent loads in flight per group
        float4 a0, b0, a1, b1, a2, b2, a3, b3;
        a0 = __ldg(r0 + c);         b0 = __ldg(r0 + c + 8);
        if (p1) { a1 = __ldg(r1 + c); b1 = __ldg(r1 + c + 8); }
        if (p2) { a2 = __ldg(r2 + c); b2 = __ldg(r2 + c + 8); }
        if (p3) { a3 = __ldg(r3 + c); b3 = __ldg(r3 + c + 8); }

        accA.x += a0.x; accA.y += a0.y; accA.z += a0.z; accA.w += a0.w;
        accB.x += b0.x; accB.y += b0.y; accB.z += b0.z; accB.w += b0.w;
        if (p1) { accA.x += a1.x; accA.y += a1.y; accA.z += a1.z; accA.w += a1.w;
                  accB.x += b1.x; accB.y += b1.y; accB.z += b1.z; accB.w += b1.w; }
        if (p2) { accA.x += a2.x; accA.y += a2.y; accA.z += a2.z; accA.w += a2.w;
                  accB.x += b2.x; accB.y += b2.y; accB.z += b2.z; accB.w += b2.w; }
        if (p3) { accA.x += a3.x; accA.y += a3.y; accA.z += a3.z; accA.w += a3.w;
                  accB.x += b3.x; accB.y += b3.y; accB.z += b3.z; accB.w += b3.w; }
    }

    accA.x *= scale; accA.y *= scale; accA.z *= scale; accA.w *= scale;
    accB.x *= scale; accB.y *= scale; accB.z *= scale; accB.w *= scale;

    float4* orow = reinterpret_cast<float4*>(out + (size_t)o * 64);
    __stcs(orow + c,     accA);
    __stcs(orow + c + 8, accB);
}

// Fallback path (round-1 atomic scatter) if sizes exceed scratch capacity.
__global__ void avgpool_scatter_kernel(const float* __restrict__ input,
                                       const int* __restrict__ rules_in,
                                       const int* __restrict__ rules_out,
                                       float* __restrict__ out,
                                       int n_rules)
{
    const float scale = 0.125f;
    long long gid = (long long)blockIdx.x * blockDim.x + threadIdx.x;
    long long total = (long long)n_rules * 16;
    if (gid >= total) return;
    int r = (int)(gid >> 4);
    int c = (int)(gid & 15);
    int rin = rules_in[r];
    int rout = rules_out[r];
    const float4* src = reinterpret_cast<const float4*>(input + (long long)rin * 64) + c;
    float4 v = *src;
    v.x *= scale; v.y *= scale; v.z *= scale; v.w *= scale;
    float* dst = out + (long long)rout * 64 + c * 4;
    asm volatile("red.global.add.v4.f32 [%0], {%1, %2, %3, %4};"
                 :: "l"(dst), "f"(v.x), "f"(v.y), "f"(v.z), "f"(v.w) : "memory");
}

extern "C" void kernel_launch(void* const* d_in, const int* in_sizes, int n_in,
                              void* d_out, int out_size)
{
    const float* input     = (const float*)d_in[0];
    const int*   rules_in  = (const int*)d_in[1];
    const int*   rules_out = (const int*)d_in[2];
    float* out = (float*)d_out;

    int n_rules = in_sizes[1];
    int n_out   = out_size / 64;

    if (n_out > NOUT_CAP || n_rules > NRULE_CAP) {
        cudaMemsetAsync(out, 0, (size_t)out_size * sizeof(float));
        long long total = (long long)n_rules * 16;
        int threads = 256;
        long long blocks = (total + threads - 1) / threads;
        avgpool_scatter_kernel<<<(unsigned)blocks, threads>>>(
            input, rules_in, rules_out, out, n_rules);
        return;
    }

    // Phase A: zero counters
    {
        int n_words4 = (n_out + 3) / 4;
        int threads = 256;
        int blocks = (n_words4 + threads - 1) / threads;
        zero_counts_kernel<<<blocks, threads>>>(n_words4);
    }

    // Phase B: invert rulebook (4 rules per thread)
    {
        int n_t = (n_rules + 3) / 4;
        int threads = 256;
        int blocks = (n_t + threads - 1) / threads;
        bucket_scatter_kernel<<<blocks, threads>>>(rules_in, rules_out, n_rules);
    }

    // Phase C: output-driven gather, 8 threads per output row
    {
        long long total = (long long)n_out * 8;
        int threads = 256;
        long long blocks = (total + threads - 1) / threads;
        gather_kernel<<<(unsigned)blocks, threads>>>(input, out, n_out);
    }
}